// round 11
// baseline (speedup 1.0000x reference)
#include <cuda_runtime.h>
#include <cuda_fp16.h>

static constexpr int BB  = 256;
static constexpr int TT  = 256;
static constexpr int MM  = 8;
static constexpr int AUX = 32;
static constexpr int HH  = 64;
static constexpr int BT  = BB * TT;     // 65536
static constexpr int NC  = HH * HH;     // 4096

static constexpr int CH   = 8;          // timesteps per fused chunk
static constexpr int NCH  = TT / CH;    // 32
static constexpr int RSTR = 4104;       // rbuf row stride in halves (4096 + 8 pad)
static constexpr float LOG2E = 1.4426950408889634f;

// Scratch (static device globals: allowed, no runtime allocation)
__device__ float    g_min[(size_t)BT * HH];  // m_in, fp32, 16.8 MB
// Wr fragments packed for LDG.128: [T=512][lane=32][j=4], j = ks*2 + b
__device__ unsigned g_wTf[NC * 4 * 32 / 8];
__device__ unsigned g_wjTf[(MM * HH) * 4 * 32 / 8]; // Wj same packing, T=64

__device__ __forceinline__ float rcp_fast(float x) {
    float r; asm("rcp.approx.ftz.f32 %0, %1;" : "=f"(r) : "f"(x)); return r;
}
__device__ __forceinline__ float ex2f(float x) {
    float r; asm("ex2.approx.ftz.f32 %0, %1;" : "=f"(r) : "f"(x)); return r;
}
__device__ __forceinline__ void mma16816(float4& d, unsigned a0, unsigned a1,
                                         unsigned a2, unsigned a3,
                                         unsigned b0, unsigned b1) {
    asm volatile(
        "mma.sync.aligned.m16n8k16.row.col.f32.f16.f16.f32 "
        "{%0,%1,%2,%3}, {%4,%5,%6,%7}, {%8,%9}, {%0,%1,%2,%3};"
        : "+f"(d.x), "+f"(d.y), "+f"(d.z), "+f"(d.w)
        : "r"(a0), "r"(a1), "r"(a2), "r"(a3), "r"(b0), "r"(b1));
}

// ---------------------------------------------------------------------------
// Weight converters into LDG.128-friendly fragment order.
// ---------------------------------------------------------------------------
__global__ __launch_bounds__(256) void k_cvt_wf(const float* __restrict__ Wr) {
    int i = blockIdx.x * 256 + threadIdx.x;   // 65536
    int j = i & 3, lane = (i >> 2) & 31, T = i >> 7;
    int b = j & 1, ks = j >> 1;
    int n = T * 8 + (lane >> 2);
    int k = ks * 16 + b * 8 + (lane & 3) * 2;
    __half2 h = __floats2half2_rn(Wr[k * NC + n], Wr[(k + 1) * NC + n]);
    g_wTf[i] = *(unsigned*)&h;
}
__global__ __launch_bounds__(256) void k_cvt_wjf(const float* __restrict__ Wj) {
    int i = blockIdx.x * 256 + threadIdx.x;   // 8192
    int j = i & 3, lane = (i >> 2) & 31, T = i >> 7;
    int b = j & 1, ks = j >> 1;
    int n = T * 8 + (lane >> 2);
    int k = ks * 16 + b * 8 + (lane & 3) * 2;
    __half2 h = __floats2half2_rn(Wj[k * (MM * HH) + n], Wj[(k + 1) * (MM * HH) + n]);
    g_wjTf[i] = *(unsigned*)&h;
}

// ---------------------------------------------------------------------------
// Phase 1b (tensor-core, atomic-free): m_in = sum_m xm * softmax_h(xa@Wj+bj).
// (unchanged from R9 — passed)
// ---------------------------------------------------------------------------
__global__ __launch_bounds__(256) void k_phase1b(const float* __restrict__ xa,
                                                 const float* __restrict__ xm,
                                                 const float* __restrict__ bj) {
    extern __shared__ __align__(16) char smem1b[];
    __half* sA    = (__half*)smem1b;                    // [32][40]
    float*  sXm   = (float*)(smem1b + 2560);            // [32][8]
    float*  sBias = (float*)(smem1b + 2560 + 1024);     // [512]
    float*  sPart = (float*)(smem1b + 2560 + 1024 + 2048); // [8][32][68]

    const int rb  = blockIdx.x;
    const int tid = threadIdx.x;

    {
        float4 v = ((const float4*)(xa + (size_t)rb * 32 * AUX))[tid];
        int row = tid >> 3, q = tid & 7;
        *(__half2*)(sA + row * 40 + q * 4)     = __floats2half2_rn(v.x, v.y);
        *(__half2*)(sA + row * 40 + q * 4 + 2) = __floats2half2_rn(v.z, v.w);
    }
    sXm[tid] = xm[(size_t)rb * 32 * MM + tid];
    if (tid < 128) ((float4*)sBias)[tid] = ((const float4*)bj)[tid];

    const int warp = tid >> 5, lane = tid & 31;
    const int g = lane >> 2, t2 = (lane & 3) * 2;
    float* myPart = sPart + warp * (32 * 68);

    uint4 bw[8];
    {
        const uint4* wj4 = (const uint4*)g_wjTf;
#pragma unroll
        for (int t = 0; t < 8; t++)
            bw[t] = wj4[(size_t)(warp * 8 + t) * 32 + lane];
    }

    __syncthreads();

#pragma unroll
    for (int mt = 0; mt < 2; mt++) {
        float4 d[8];
#pragma unroll
        for (int t = 0; t < 8; t++) d[t] = make_float4(0.f, 0.f, 0.f, 0.f);
#pragma unroll
        for (int ks = 0; ks < 2; ks++) {
            const __half* Ab = sA + mt * 16 * 40 + ks * 16;
            unsigned a0 = *(const unsigned*)(Ab + g * 40 + t2);
            unsigned a1 = *(const unsigned*)(Ab + (g + 8) * 40 + t2);
            unsigned a2 = *(const unsigned*)(Ab + g * 40 + t2 + 8);
            unsigned a3 = *(const unsigned*)(Ab + (g + 8) * 40 + t2 + 8);
#pragma unroll
            for (int t = 0; t < 8; t++) {
                unsigned b0 = ks ? bw[t].z : bw[t].x;
                unsigned b1 = ks ? bw[t].w : bw[t].y;
                mma16816(d[t], a0, a1, a2, a3, b0, b1);
            }
        }

        float v0[16], v1[16];
#pragma unroll
        for (int t = 0; t < 8; t++) {
            float bx = sBias[warp * 64 + t * 8 + t2];
            float by = sBias[warp * 64 + t * 8 + t2 + 1];
            v0[2 * t]     = d[t].x + bx; v0[2 * t + 1] = d[t].y + by;
            v1[2 * t]     = d[t].z + bx; v1[2 * t + 1] = d[t].w + by;
        }
        float s0 = 0.f, s1 = 0.f;
#pragma unroll
        for (int j = 0; j < 16; j++) {
            v0[j] = ex2f(v0[j] * LOG2E); s0 += v0[j];
            v1[j] = ex2f(v1[j] * LOG2E); s1 += v1[j];
        }
#pragma unroll
        for (int o = 2; o; o >>= 1) {
            s0 += __shfl_xor_sync(0xffffffffu, s0, o);
            s1 += __shfl_xor_sync(0xffffffffu, s1, o);
        }
        const int rg = mt * 16 + g;
        float f0 = sXm[rg * MM + warp] * rcp_fast(s0);
        float f1 = sXm[(rg + 8) * MM + warp] * rcp_fast(s1);
#pragma unroll
        for (int t = 0; t < 8; t++) {
            int h = t * 8 + t2;
            *(float2*)(myPart + rg * 68 + h) =
                make_float2(v0[2 * t] * f0, v0[2 * t + 1] * f0);
            *(float2*)(myPart + (rg + 8) * 68 + h) =
                make_float2(v1[2 * t] * f1, v1[2 * t + 1] * f1);
        }
    }
    __syncthreads();

    float4* go = (float4*)(g_min + (size_t)rb * 32 * HH);
#pragma unroll
    for (int j = 0; j < 2; j++) {
        int e4 = tid * 2 + j;
        int row = e4 >> 4, q = e4 & 15;
        float4 s = make_float4(0.f, 0.f, 0.f, 0.f);
#pragma unroll
        for (int w2 = 0; w2 < 8; w2++) {
            float4 v = *(const float4*)(sPart + w2 * 2176 + row * 68 + q * 4);
            s.x += v.x; s.y += v.y; s.z += v.z; s.w += v.w;
        }
        go[e4] = s;
    }
}

// ---------------------------------------------------------------------------
// Fused r-compute + scan, 2 batches/CTA, 512 threads, grid 128.
// R10: pipelined fragment loads, unnormalized-exp rbuf + inv folded into the
// scan (sInv table), vectorized scan c-loads.
// smem map (bytes):
//   rbuf   0       131328   [16][RSTR] fp16 unnormalized exp
//   sA     131328  1280     [16][40] fp16 (xa * log2e)
//   sMinC  132608  4096     [2][CH][64] f32
//   sp     136704  4096     [16][64] f32 scan partials
//   scRaw  140800  512      [2][64] f32 raw c
//   scHat  141312  512      [2][64] f32 c * inv (current step)
//   sInv   141824  4096     [2][8][64] f32 row-softmax reciprocals
//   sBr    145920  16384    [4096] f32 bias * log2e
// total 162304
// ---------------------------------------------------------------------------
__global__ __launch_bounds__(512, 1) void k_fused(const float* __restrict__ xa,
                                                  const float* __restrict__ br,
                                                  const float* __restrict__ Wo,
                                                  const float* __restrict__ bo,
                                                  const float* __restrict__ Wfc,
                                                  const float* __restrict__ bfc,
                                                  float* __restrict__ out) {
    extern __shared__ __align__(16) char smemf[];
    __half* rbuf  = (__half*)smemf;
    __half* sA    = (__half*)(smemf + 131328);
    float*  sMinC = (float*)(smemf + 132608);
    float*  sp    = (float*)(smemf + 136704);
    float*  scRaw = (float*)(smemf + 140800);
    float*  scHat = (float*)(smemf + 141312);
    float*  sInv  = (float*)(smemf + 141824);
    float*  sBr   = (float*)(smemf + 145920);

    const int b0  = blockIdx.x * 2;
    const int tid = threadIdx.x;
    const int warp = tid >> 5, lane = tid & 31;
    const int g = lane >> 2, t2 = (lane & 3) * 2;
    const int wb = warp >> 3, w8 = warp & 7;   // scan: batch, h-octet

    if (tid < 128) scRaw[tid] = 0.f;
    // stage log2e-scaled bias once (constant across chunks)
    for (int i = tid; i < 1024; i += 512) {
        float4 v = ((const float4*)br)[i];
        v.x *= LOG2E; v.y *= LOG2E; v.z *= LOG2E; v.w *= LOG2E;
        ((float4*)sBr)[i] = v;
    }

    const float* mb0 = g_min + (size_t)b0 * TT * HH;
    const float* mb1 = g_min + (size_t)(b0 + 1) * TT * HH;
    const uint4* wT4 = (const uint4*)g_wTf;

    for (int ch = 0; ch < NCH; ch++) {
        const int t0 = ch * CH;
        __syncthreads();   // rbuf/sA free from previous chunk's scan
        // stage xa chunk (both batches), pre-scaled by log2e -> fp16 sA
        if (tid < 256) {
            int row = tid >> 4, q = tid & 15;           // 16 rows x 16 float2
            const float* src = (row < 8)
                ? xa + ((size_t)b0 * TT + t0 + row) * AUX + q * 2
                : xa + ((size_t)(b0 + 1) * TT + t0 + row - 8) * AUX + q * 2;
            float2 v = *(const float2*)src;
            *(__half2*)(sA + row * 40 + q * 2) =
                __floats2half2_rn(v.x * LOG2E, v.y * LOG2E);
        }
        // stage m_in chunks (2 x 512 f32 = 512 float2)
        {
            int bsel = tid >> 8, i = tid & 255;
            const float* mbx = bsel ? mb1 : mb0;
            ((float2*)sMinC)[bsel * 256 + i] =
                ((const float2*)(mbx + (size_t)t0 * HH))[i];
        }
        __syncthreads();

        // A fragments (same for all column iterations)
        unsigned a0[2], a1[2], a2[2], a3[2];
#pragma unroll
        for (int ks = 0; ks < 2; ks++) {
            const __half* Ab = sA + ks * 16;
            a0[ks] = *(const unsigned*)(Ab + g * 40 + t2);
            a1[ks] = *(const unsigned*)(Ab + (g + 8) * 40 + t2);
            a2[ks] = *(const unsigned*)(Ab + g * 40 + t2 + 8);
            a3[ks] = *(const unsigned*)(Ab + (g + 8) * 40 + t2 + 8);
        }

        // prefetch it=0 fragments
        uint4 bw[8];
        {
            const size_t tb = (size_t)(warp * 8) * 32 + lane;
#pragma unroll
            for (int t = 0; t < 8; t++) bw[t] = wT4[tb + t * 32];
        }

        // compute r chunk: warp covers h = it*16 + warp (64 k cols each)
#pragma unroll 1
        for (int it = 0; it < 4; it++) {
            const int col0 = it * 1024 + warp * 64;
            // prefetch next it's fragments (hidden behind mma + epilogue)
            uint4 bwn[8];
            if (it < 3) {
                const size_t tbn = (size_t)((it + 1) * 128 + warp * 8) * 32 + lane;
#pragma unroll
                for (int t = 0; t < 8; t++) bwn[t] = wT4[tbn + t * 32];
            }

            float4 d[8];
#pragma unroll
            for (int t = 0; t < 8; t++) d[t] = make_float4(0.f, 0.f, 0.f, 0.f);
#pragma unroll
            for (int t = 0; t < 8; t++) {
                mma16816(d[t], a0[0], a1[0], a2[0], a3[0], bw[t].x, bw[t].y);
                mma16816(d[t], a0[1], a1[1], a2[1], a3[1], bw[t].z, bw[t].w);
            }

            // epilogue: unnormalized exp -> rbuf immediately; sums -> sInv
            float s0 = 0.f, s1 = 0.f;
#pragma unroll
            for (int t = 0; t < 8; t++) {
                float2 bb = *(const float2*)(sBr + col0 + t * 8 + t2);
                float e0x = ex2f(d[t].x + bb.x);
                float e0y = ex2f(d[t].y + bb.y);
                float e1x = ex2f(d[t].z + bb.x);
                float e1y = ex2f(d[t].w + bb.y);
                s0 += e0x + e0y;
                s1 += e1x + e1y;
                *(__half2*)(rbuf + g * RSTR + col0 + t * 8 + t2) =
                    __floats2half2_rn(e0x, e0y);
                *(__half2*)(rbuf + (8 + g) * RSTR + col0 + t * 8 + t2) =
                    __floats2half2_rn(e1x, e1y);
            }
#pragma unroll
            for (int o = 2; o; o >>= 1) {
                s0 += __shfl_xor_sync(0xffffffffu, s0, o);
                s1 += __shfl_xor_sync(0xffffffffu, s1, o);
            }
            if ((lane & 3) == 0) {
                int h = it * 16 + warp;                 // this warp-it's h
                sInv[g * 64 + h]       = rcp_fast(s0);  // [b0][row g][h]
                sInv[512 + g * 64 + h] = rcp_fast(s1);  // [b1][row g][h]
            }
#pragma unroll
            for (int t = 0; t < 8; t++) bw[t] = bwn[t];
        }
        __syncthreads();

        // fixup: fold this chunk's row-0 inv into the carried c
        if (tid < 128) {
            int bsel = tid >> 6, k = tid & 63;
            scHat[tid] = scRaw[tid] * sInv[bsel * 512 + k];
        }
        __syncthreads();

        // scan CH steps, both batches in parallel.
        // warp (wb, w8): batch wb, h-rows w8*8..+7, lane -> cols lane*2,+1
        for (int tt = 0; tt < CH; tt++) {
            const __half* rr = rbuf + (wb * 8 + tt) * RSTR + (w8 * 8) * HH + lane * 2;
            const float* cbase = scHat + wb * 64 + w8 * 8;
            float4 cA = *(const float4*)cbase;
            float4 cB = *(const float4*)(cbase + 4);
            float2 p = make_float2(0.f, 0.f);
#pragma unroll
            for (int i = 0; i < 8; i++) {
                float c = (i < 4) ? ((const float*)&cA)[i] : ((const float*)&cB)[i - 4];
                float2 f = __half22float2(*(const __half2*)(rr + i * HH));
                p.x = fmaf(c, f.x, p.x);
                p.y = fmaf(c, f.y, p.y);
            }
            *(float2*)(sp + (wb * 8 + w8) * 64 + lane * 2) = p;
            __syncthreads();
            if (tid < 128) {
                int bsel = tid >> 6, k = tid & 63;
                float v = sMinC[bsel * 512 + tt * 64 + k];
#pragma unroll
                for (int q8 = 0; q8 < 8; q8++) v += sp[(bsel * 8 + q8) * 64 + k];
                scRaw[tid] = v;
                if (tt < CH - 1)
                    scHat[tid] = v * sInv[bsel * 512 + (tt + 1) * 64 + k];
            }
            __syncthreads();
        }
    }

    // tail: gate + fc on last timestep; c_final (2 batches)
    if (tid < 128) {
        int bsel = tid >> 6, k = tid & 63;
        int b = b0 + bsel;
        const float* xarow = xa + ((size_t)b * TT + (TT - 1)) * AUX;
        float acc = bo[k];
#pragma unroll
        for (int a = 0; a < AUX; a++) acc = fmaf(xarow[a], Wo[a * HH + k], acc);
        float o = 1.f / (1.f + __expf(-acc));
        float cfin = scRaw[bsel * 64 + k];
        out[BB + b * HH + k] = cfin;            // c_final at offset 256
        sp[bsel * 64 + k] = o * cfin * Wfc[k];
    }
    __syncthreads();
    if (tid < 2) {
        float s = bfc[0];
        for (int i = 0; i < HH; i++) s += sp[tid * 64 + i];
        out[b0 + tid] = s;                      // out[b, 0]
    }
}

extern "C" void kernel_launch(void* const* d_in, const int* in_sizes, int n_in,
                              void* d_out, int out_size) {
    const float* xm  = (const float*)d_in[0];
    const float* xa  = (const float*)d_in[1];
    const float* Wj  = (const float*)d_in[2];
    const float* bj  = (const float*)d_in[3];
    const float* Wr  = (const float*)d_in[4];
    const float* br  = (const float*)d_in[5];
    const float* Wo  = (const float*)d_in[6];
    const float* bo  = (const float*)d_in[7];
    const float* Wfc = (const float*)d_in[8];
    const float* bfc = (const float*)d_in[9];
    float* out = (float*)d_out;

    cudaFuncSetAttribute(k_phase1b, cudaFuncAttributeMaxDynamicSharedMemorySize, 75264);
    cudaFuncSetAttribute(k_fused,   cudaFuncAttributeMaxDynamicSharedMemorySize, 162304);

    k_cvt_wf <<<256, 256>>>(Wr);                       // Wr -> packed fragments
    k_cvt_wjf<<<32, 256>>>(Wj);                        // Wj -> packed fragments
    k_phase1b<<<BT / 32, 256, 75264>>>(xa, xm, bj);    // m_in
    k_fused  <<<BB / 2, 512, 162304>>>(xa, br, Wo, bo, Wfc, bfc, out);
}

// round 13
// speedup vs baseline: 1.1679x; 1.1679x over previous
#include <cuda_runtime.h>
#include <cuda_fp16.h>

static constexpr int BB  = 256;
static constexpr int TT  = 256;
static constexpr int MM  = 8;
static constexpr int AUX = 32;
static constexpr int HH  = 64;
static constexpr int BT  = BB * TT;     // 65536
static constexpr int NC  = HH * HH;     // 4096

static constexpr int CH   = 8;          // timesteps per fused chunk
static constexpr int NCH  = TT / CH;    // 32
static constexpr int RSTR = 4104;       // rbuf row stride in halves (4096 + 8 pad)
static constexpr float LOG2E = 1.4426950408889634f;

// Scratch (static device globals: allowed, no runtime allocation)
__device__ float    g_min[(size_t)BT * HH];  // m_in, fp32, 16.8 MB
// Wr fragments packed for LDG.128: [T=512][lane=32][j=4], j = ks*2 + b
__device__ unsigned g_wTf[NC * 4 * 32 / 8];
__device__ unsigned g_wjTf[(MM * HH) * 4 * 32 / 8]; // Wj same packing, T=64

__device__ __forceinline__ float rcp_fast(float x) {
    float r; asm("rcp.approx.ftz.f32 %0, %1;" : "=f"(r) : "f"(x)); return r;
}
__device__ __forceinline__ float ex2f(float x) {
    float r; asm("ex2.approx.ftz.f32 %0, %1;" : "=f"(r) : "f"(x)); return r;
}
__device__ __forceinline__ void mma16816(float4& d, unsigned a0, unsigned a1,
                                         unsigned a2, unsigned a3,
                                         unsigned b0, unsigned b1) {
    asm volatile(
        "mma.sync.aligned.m16n8k16.row.col.f32.f16.f16.f32 "
        "{%0,%1,%2,%3}, {%4,%5,%6,%7}, {%8,%9}, {%0,%1,%2,%3};"
        : "+f"(d.x), "+f"(d.y), "+f"(d.z), "+f"(d.w)
        : "r"(a0), "r"(a1), "r"(a2), "r"(a3), "r"(b0), "r"(b1));
}

// ---------------------------------------------------------------------------
// Weight converters into LDG.128-friendly fragment order.
// ---------------------------------------------------------------------------
__global__ __launch_bounds__(256) void k_cvt_wf(const float* __restrict__ Wr) {
    int i = blockIdx.x * 256 + threadIdx.x;   // 65536
    int j = i & 3, lane = (i >> 2) & 31, T = i >> 7;
    int b = j & 1, ks = j >> 1;
    int n = T * 8 + (lane >> 2);
    int k = ks * 16 + b * 8 + (lane & 3) * 2;
    __half2 h = __floats2half2_rn(Wr[k * NC + n], Wr[(k + 1) * NC + n]);
    g_wTf[i] = *(unsigned*)&h;
}
__global__ __launch_bounds__(256) void k_cvt_wjf(const float* __restrict__ Wj) {
    int i = blockIdx.x * 256 + threadIdx.x;   // 8192
    int j = i & 3, lane = (i >> 2) & 31, T = i >> 7;
    int b = j & 1, ks = j >> 1;
    int n = T * 8 + (lane >> 2);
    int k = ks * 16 + b * 8 + (lane & 3) * 2;
    __half2 h = __floats2half2_rn(Wj[k * (MM * HH) + n], Wj[(k + 1) * (MM * HH) + n]);
    g_wjTf[i] = *(unsigned*)&h;
}

// ---------------------------------------------------------------------------
// Phase 1b (tensor-core, atomic-free): m_in = sum_m xm * softmax_h(xa@Wj+bj).
// (unchanged from R9 — passed)
// ---------------------------------------------------------------------------
__global__ __launch_bounds__(256) void k_phase1b(const float* __restrict__ xa,
                                                 const float* __restrict__ xm,
                                                 const float* __restrict__ bj) {
    extern __shared__ __align__(16) char smem1b[];
    __half* sA    = (__half*)smem1b;                    // [32][40]
    float*  sXm   = (float*)(smem1b + 2560);            // [32][8]
    float*  sBias = (float*)(smem1b + 2560 + 1024);     // [512]
    float*  sPart = (float*)(smem1b + 2560 + 1024 + 2048); // [8][32][68]

    const int rb  = blockIdx.x;
    const int tid = threadIdx.x;

    {
        float4 v = ((const float4*)(xa + (size_t)rb * 32 * AUX))[tid];
        int row = tid >> 3, q = tid & 7;
        *(__half2*)(sA + row * 40 + q * 4)     = __floats2half2_rn(v.x, v.y);
        *(__half2*)(sA + row * 40 + q * 4 + 2) = __floats2half2_rn(v.z, v.w);
    }
    sXm[tid] = xm[(size_t)rb * 32 * MM + tid];
    if (tid < 128) ((float4*)sBias)[tid] = ((const float4*)bj)[tid];

    const int warp = tid >> 5, lane = tid & 31;
    const int g = lane >> 2, t2 = (lane & 3) * 2;
    float* myPart = sPart + warp * (32 * 68);

    uint4 bw[8];
    {
        const uint4* wj4 = (const uint4*)g_wjTf;
#pragma unroll
        for (int t = 0; t < 8; t++)
            bw[t] = wj4[(size_t)(warp * 8 + t) * 32 + lane];
    }

    __syncthreads();

#pragma unroll
    for (int mt = 0; mt < 2; mt++) {
        float4 d[8];
#pragma unroll
        for (int t = 0; t < 8; t++) d[t] = make_float4(0.f, 0.f, 0.f, 0.f);
#pragma unroll
        for (int ks = 0; ks < 2; ks++) {
            const __half* Ab = sA + mt * 16 * 40 + ks * 16;
            unsigned a0 = *(const unsigned*)(Ab + g * 40 + t2);
            unsigned a1 = *(const unsigned*)(Ab + (g + 8) * 40 + t2);
            unsigned a2 = *(const unsigned*)(Ab + g * 40 + t2 + 8);
            unsigned a3 = *(const unsigned*)(Ab + (g + 8) * 40 + t2 + 8);
#pragma unroll
            for (int t = 0; t < 8; t++) {
                unsigned b0 = ks ? bw[t].z : bw[t].x;
                unsigned b1 = ks ? bw[t].w : bw[t].y;
                mma16816(d[t], a0, a1, a2, a3, b0, b1);
            }
        }

        float v0[16], v1[16];
#pragma unroll
        for (int t = 0; t < 8; t++) {
            float bx = sBias[warp * 64 + t * 8 + t2];
            float by = sBias[warp * 64 + t * 8 + t2 + 1];
            v0[2 * t]     = d[t].x + bx; v0[2 * t + 1] = d[t].y + by;
            v1[2 * t]     = d[t].z + bx; v1[2 * t + 1] = d[t].w + by;
        }
        float s0 = 0.f, s1 = 0.f;
#pragma unroll
        for (int j = 0; j < 16; j++) {
            v0[j] = ex2f(v0[j] * LOG2E); s0 += v0[j];
            v1[j] = ex2f(v1[j] * LOG2E); s1 += v1[j];
        }
#pragma unroll
        for (int o = 2; o; o >>= 1) {
            s0 += __shfl_xor_sync(0xffffffffu, s0, o);
            s1 += __shfl_xor_sync(0xffffffffu, s1, o);
        }
        const int rg = mt * 16 + g;
        float f0 = sXm[rg * MM + warp] * rcp_fast(s0);
        float f1 = sXm[(rg + 8) * MM + warp] * rcp_fast(s1);
#pragma unroll
        for (int t = 0; t < 8; t++) {
            int h = t * 8 + t2;
            *(float2*)(myPart + rg * 68 + h) =
                make_float2(v0[2 * t] * f0, v0[2 * t + 1] * f0);
            *(float2*)(myPart + (rg + 8) * 68 + h) =
                make_float2(v1[2 * t] * f1, v1[2 * t + 1] * f1);
        }
    }
    __syncthreads();

    float4* go = (float4*)(g_min + (size_t)rb * 32 * HH);
#pragma unroll
    for (int j = 0; j < 2; j++) {
        int e4 = tid * 2 + j;
        int row = e4 >> 4, q = e4 & 15;
        float4 s = make_float4(0.f, 0.f, 0.f, 0.f);
#pragma unroll
        for (int w2 = 0; w2 < 8; w2++) {
            float4 v = *(const float4*)(sPart + w2 * 2176 + row * 68 + q * 4);
            s.x += v.x; s.y += v.y; s.z += v.z; s.w += v.w;
        }
        go[e4] = s;
    }
}

// ---------------------------------------------------------------------------
// Fused r-compute + scan, 2 batches/CTA, 512 threads, grid 128. Base = R9.
// R12: role-split warps (scan on warps 0-7 with named bar.sync 1,256;
// warps 8-15 stage next chunk into double-buffered sA/sMinC). The R11
// aliasing bug (pointer walk across separate float4 locals) is fixed by
// loading carried c into ONE float4[4] array and indexing it with
// compile-time constants.
// smem map (bytes):
//   rbuf   0       131328   [16][RSTR] fp16 normalized r
//   sA     131328  2560     [2][16][40] fp16 (xa * log2e), double-buffered
//   sMinC  133888  8192     [2][2][CH][64] f32, double-buffered
//   sp     142080  2048     [8][64] f32 scan partials
//   sc     144128  512      [2][64] f32 cell state
//   sBr    144640  16384    [4096] f32 bias * log2e
// total 161024
// ---------------------------------------------------------------------------
__global__ __launch_bounds__(512, 1) void k_fused(const float* __restrict__ xa,
                                                  const float* __restrict__ br,
                                                  const float* __restrict__ Wo,
                                                  const float* __restrict__ bo,
                                                  const float* __restrict__ Wfc,
                                                  const float* __restrict__ bfc,
                                                  float* __restrict__ out) {
    extern __shared__ __align__(16) char smemf[];
    __half* rbuf  = (__half*)smemf;
    __half* sA    = (__half*)(smemf + 131328);   // [2][16*40]
    float*  sMinC = (float*)(smemf + 133888);    // [2][1024]
    float*  sp    = (float*)(smemf + 142080);    // [8][64]
    float*  sc    = (float*)(smemf + 144128);    // [2][64]
    float*  sBr   = (float*)(smemf + 144640);    // [4096]

    const int b0  = blockIdx.x * 2;
    const int tid = threadIdx.x;
    const int warp = tid >> 5, lane = tid & 31;
    const int g = lane >> 2, t2 = (lane & 3) * 2;

    if (tid < 128) sc[tid] = 0.f;
    // stage log2e-scaled bias once (constant across chunks)
    for (int i = tid; i < 1024; i += 512) {
        float4 v = ((const float4*)br)[i];
        v.x *= LOG2E; v.y *= LOG2E; v.z *= LOG2E; v.w *= LOG2E;
        ((float4*)sBr)[i] = v;
    }

    const float* mb0 = g_min + (size_t)b0 * TT * HH;
    const float* mb1 = g_min + (size_t)(b0 + 1) * TT * HH;
    const uint4* wT4 = (const uint4*)g_wTf;

    // prologue: stage chunk 0 into buffer 0
    if (tid < 256) {
        int row = tid >> 4, q = tid & 15;
        const float* src = (row < 8)
            ? xa + ((size_t)b0 * TT + row) * AUX + q * 2
            : xa + ((size_t)(b0 + 1) * TT + row - 8) * AUX + q * 2;
        float2 v = *(const float2*)src;
        *(__half2*)(sA + row * 40 + q * 2) =
            __floats2half2_rn(v.x * LOG2E, v.y * LOG2E);
    }
    {
        int bsel = tid >> 8, i = tid & 255;
        const float* mbx = bsel ? mb1 : mb0;
        ((float2*)(sMinC + bsel * 512))[i] = ((const float2*)mbx)[i];
    }
    __syncthreads();

    for (int ch = 0; ch < NCH; ch++) {
        const int cb = ch & 1;
        const __half* sAc = sA + cb * 640;       // 640 halves = 16*40
        const float*  sMc = sMinC + cb * 1024;

        // ---- compute phase: all 16 warps ----
        unsigned a0[2], a1[2], a2[2], a3[2];
#pragma unroll
        for (int ks = 0; ks < 2; ks++) {
            const __half* Ab = sAc + ks * 16;
            a0[ks] = *(const unsigned*)(Ab + g * 40 + t2);
            a1[ks] = *(const unsigned*)(Ab + (g + 8) * 40 + t2);
            a2[ks] = *(const unsigned*)(Ab + g * 40 + t2 + 8);
            a3[ks] = *(const unsigned*)(Ab + (g + 8) * 40 + t2 + 8);
        }

#pragma unroll 1
        for (int it = 0; it < 4; it++) {
            const int col0 = it * 1024 + warp * 64;
            uint4 bw[8];
            {
                const size_t tb = (size_t)(it * 128 + warp * 8) * 32 + lane;
#pragma unroll
                for (int t = 0; t < 8; t++) bw[t] = wT4[tb + t * 32];
            }
            float4 d[8];
#pragma unroll
            for (int t = 0; t < 8; t++) d[t] = make_float4(0.f, 0.f, 0.f, 0.f);
#pragma unroll
            for (int t = 0; t < 8; t++) {
                mma16816(d[t], a0[0], a1[0], a2[0], a3[0], bw[t].x, bw[t].y);
                mma16816(d[t], a0[1], a1[1], a2[1], a3[1], bw[t].z, bw[t].w);
            }

            // epilogue (no max-pass): rows g (b0) and g+8 (b1)
            float v0[16], v1[16];
            float s0 = 0.f, s1 = 0.f;
#pragma unroll
            for (int t = 0; t < 8; t++) {
                float2 bb = *(const float2*)(sBr + col0 + t * 8 + t2);
                v0[2 * t]     = ex2f(d[t].x + bb.x); s0 += v0[2 * t];
                v0[2 * t + 1] = ex2f(d[t].y + bb.y); s0 += v0[2 * t + 1];
                v1[2 * t]     = ex2f(d[t].z + bb.x); s1 += v1[2 * t];
                v1[2 * t + 1] = ex2f(d[t].w + bb.y); s1 += v1[2 * t + 1];
            }
#pragma unroll
            for (int o = 2; o; o >>= 1) {
                s0 += __shfl_xor_sync(0xffffffffu, s0, o);
                s1 += __shfl_xor_sync(0xffffffffu, s1, o);
            }
            float inv0 = rcp_fast(s0), inv1 = rcp_fast(s1);
#pragma unroll
            for (int t = 0; t < 8; t++) {
                __half2 h0 = __floats2half2_rn(v0[2 * t] * inv0, v0[2 * t + 1] * inv0);
                __half2 h1 = __floats2half2_rn(v1[2 * t] * inv1, v1[2 * t + 1] * inv1);
                *(__half2*)(rbuf + g * RSTR + col0 + t * 8 + t2)       = h0;
                *(__half2*)(rbuf + (8 + g) * RSTR + col0 + t * 8 + t2) = h1;
            }
        }
        __syncthreads();   // rbuf complete

        // ---- scan (warps 0-7) || stage next chunk (warps 8-15) ----
        if (warp < 8) {
            const int wb = warp >> 2, w4 = warp & 3;
            for (int tt = 0; tt < CH; tt++) {
                const __half* rr = rbuf + (wb * 8 + tt) * RSTR
                                 + (w4 * 16) * HH + lane * 2;
                const float* cbase = sc + wb * 64 + w4 * 16;
                float4 cv[4];                    // ONE contiguous object
#pragma unroll
                for (int i = 0; i < 4; i++)
                    cv[i] = *(const float4*)(cbase + i * 4);
                const float* cf = (const float*)cv;
                float2 pa = make_float2(0.f, 0.f);
                float2 pb = make_float2(0.f, 0.f);
#pragma unroll
                for (int i = 0; i < 8; i++) {
                    float ca = cf[i], cb2 = cf[i + 8];
                    float2 fa = __half22float2(*(const __half2*)(rr + i * HH));
                    float2 fb = __half22float2(*(const __half2*)(rr + (i + 8) * HH));
                    pa.x = fmaf(ca, fa.x, pa.x);
                    pa.y = fmaf(ca, fa.y, pa.y);
                    pb.x = fmaf(cb2, fb.x, pb.x);
                    pb.y = fmaf(cb2, fb.y, pb.y);
                }
                *(float2*)(sp + (wb * 4 + w4) * 64 + lane * 2) =
                    make_float2(pa.x + pb.x, pa.y + pb.y);
                asm volatile("bar.sync 1, 256;" ::: "memory");
                if (tid < 128) {
                    int bsel = tid >> 6, k = tid & 63;
                    float v = sMc[bsel * 512 + tt * 64 + k];
#pragma unroll
                    for (int q4 = 0; q4 < 4; q4++)
                        v += sp[(bsel * 4 + q4) * 64 + k];
                    sc[tid] = v;
                }
                asm volatile("bar.sync 1, 256;" ::: "memory");
            }
        } else if (ch + 1 < NCH) {
            const int nb = cb ^ 1;
            const int t0n = (ch + 1) * CH;
            const int stid = tid - 256;          // 0..255
            {
                int row = stid >> 4, q = stid & 15;
                const float* src = (row < 8)
                    ? xa + ((size_t)b0 * TT + t0n + row) * AUX + q * 2
                    : xa + ((size_t)(b0 + 1) * TT + t0n + row - 8) * AUX + q * 2;
                float2 v = *(const float2*)src;
                *(__half2*)(sA + nb * 640 + row * 40 + q * 2) =
                    __floats2half2_rn(v.x * LOG2E, v.y * LOG2E);
            }
#pragma unroll
            for (int j = 0; j < 2; j++) {
                int idx = stid * 2 + j;          // 0..511
                int bsel = idx >> 8, i = idx & 255;
                const float* mbx = bsel ? mb1 : mb0;
                ((float2*)(sMinC + nb * 1024 + bsel * 512))[i] =
                    ((const float2*)(mbx + (size_t)t0n * HH))[i];
            }
        }
        __syncthreads();   // scan done (sc final for chunk) + staging done
    }

    // tail: gate + fc on last timestep; c_final (2 batches)
    if (tid < 128) {
        int bsel = tid >> 6, k = tid & 63;
        int b = b0 + bsel;
        const float* xarow = xa + ((size_t)b * TT + (TT - 1)) * AUX;
        float acc = bo[k];
#pragma unroll
        for (int a = 0; a < AUX; a++) acc = fmaf(xarow[a], Wo[a * HH + k], acc);
        float o = 1.f / (1.f + __expf(-acc));
        float cfin = sc[bsel * 64 + k];
        out[BB + b * HH + k] = cfin;            // c_final at offset 256
        sp[bsel * 64 + k] = o * cfin * Wfc[k];
    }
    __syncthreads();
    if (tid < 2) {
        float s = bfc[0];
        for (int i = 0; i < HH; i++) s += sp[tid * 64 + i];
        out[b0 + tid] = s;                      // out[b, 0]
    }
}

extern "C" void kernel_launch(void* const* d_in, const int* in_sizes, int n_in,
                              void* d_out, int out_size) {
    const float* xm  = (const float*)d_in[0];
    const float* xa  = (const float*)d_in[1];
    const float* Wj  = (const float*)d_in[2];
    const float* bj  = (const float*)d_in[3];
    const float* Wr  = (const float*)d_in[4];
    const float* br  = (const float*)d_in[5];
    const float* Wo  = (const float*)d_in[6];
    const float* bo  = (const float*)d_in[7];
    const float* Wfc = (const float*)d_in[8];
    const float* bfc = (const float*)d_in[9];
    float* out = (float*)d_out;

    cudaFuncSetAttribute(k_phase1b, cudaFuncAttributeMaxDynamicSharedMemorySize, 75264);
    cudaFuncSetAttribute(k_fused,   cudaFuncAttributeMaxDynamicSharedMemorySize, 161024);

    k_cvt_wf <<<256, 256>>>(Wr);                       // Wr -> packed fragments
    k_cvt_wjf<<<32, 256>>>(Wj);                        // Wj -> packed fragments
    k_phase1b<<<BT / 32, 256, 75264>>>(xa, xm, bj);    // m_in
    k_fused  <<<BB / 2, 512, 161024>>>(xa, br, Wo, bo, Wfc, bfc, out);
}